// round 1
// baseline (speedup 1.0000x reference)
#include <cuda_runtime.h>
#include <cuda_bf16.h>
#include <math.h>

// ---------------- problem constants ----------------
#define NB 5            // batch
#define SEQ 1024
#define T 1025          // SEQ + cls
#define DM 512
#define NHEAD 8
#define HD 64
#define DFF 2048
#define NL 4
#define NTOK 51
#define MLPD 256
#define CLASSES 7
#define GH 3
#define GHID 64
#define GCLS 5
#define MROWS (NB * T)          // 5125
#define GAT_GRAPHS (SEQ * 5)    // 5120
#define OUT_GAT_BASE (NB * CLASSES)  // 35

// ---------------- scratch (device globals; no allocation) ----------------
__device__ float g_h [MROWS * DM];
__device__ float g_q [MROWS * DM];
__device__ float g_k [MROWS * DM];
__device__ float g_v [MROWS * DM];
__device__ float g_ao[MROWS * DM];
__device__ float g_t [MROWS * DM];
__device__ float g_ff[MROWS * DFF];

// ---------------- encoder: h = concat(cls, x@W_enc+b) + pos ----------------
__global__ void enc_kernel(const float* __restrict__ x,
                           const float* __restrict__ W_enc,
                           const float* __restrict__ b_enc,
                           const float* __restrict__ cls_tok,
                           const float* __restrict__ pos_emb,
                           float* __restrict__ h)
{
    int row = blockIdx.x;            // 0..5124
    int b = row / T, t = row % T;
    int tid = threadIdx.x;           // 128
    float* hr = h + (size_t)row * DM;
    if (t == 0) {
        for (int d = tid; d < DM; d += 128)
            hr[d] = cls_tok[d] + pos_emb[d];
        return;
    }
    __shared__ float xs[NTOK];
    if (tid < NTOK) xs[tid] = x[(size_t)b * SEQ * NTOK + (size_t)(t - 1) * NTOK + tid];
    __syncthreads();
    for (int d = tid; d < DM; d += 128) {
        float acc = b_enc[d] + pos_emb[(size_t)t * DM + d];
        #pragma unroll 17
        for (int kk = 0; kk < NTOK; kk++)
            acc += xs[kk] * W_enc[kk * DM + d];
        hr[d] = acc;
    }
}

// ---------------- generic tiled GEMM: C = A(MxK) @ B(KxN) + bias, opt relu ----------------
// BM=BN=64, BK=16, 256 threads, 4x4 per thread
__global__ __launch_bounds__(256) void gemm_kernel(
    const float* __restrict__ A, const float* __restrict__ B,
    const float* __restrict__ bias, float* __restrict__ C,
    int M, int N, int K, int relu)
{
    __shared__ float As[16][64];
    __shared__ float Bs[16][64];
    int tid = threadIdx.x;
    int ty = tid >> 4, tx = tid & 15;
    int bm = blockIdx.y * 64;
    int bn = blockIdx.x * 64;

    int arow = tid >> 2;             // 0..63
    int acol = (tid & 3) << 2;       // 0,4,8,12
    int brow = tid >> 4;             // 0..15
    int bcol = (tid & 15) << 2;      // 0..60

    float acc[4][4] = {};
    for (int k0 = 0; k0 < K; k0 += 16) {
        int gm = bm + arow;
        float4 av = make_float4(0.f, 0.f, 0.f, 0.f);
        if (gm < M) av = *(const float4*)(A + (size_t)gm * K + k0 + acol);
        As[acol + 0][arow] = av.x;
        As[acol + 1][arow] = av.y;
        As[acol + 2][arow] = av.z;
        As[acol + 3][arow] = av.w;
        float4 bv = *(const float4*)(B + (size_t)(k0 + brow) * N + bn + bcol);
        *(float4*)&Bs[brow][bcol] = bv;
        __syncthreads();
        #pragma unroll
        for (int k = 0; k < 16; k++) {
            float4 a = *(float4*)&As[k][ty << 2];
            float4 b = *(float4*)&Bs[k][tx << 2];
            acc[0][0] += a.x * b.x; acc[0][1] += a.x * b.y; acc[0][2] += a.x * b.z; acc[0][3] += a.x * b.w;
            acc[1][0] += a.y * b.x; acc[1][1] += a.y * b.y; acc[1][2] += a.y * b.z; acc[1][3] += a.y * b.w;
            acc[2][0] += a.z * b.x; acc[2][1] += a.z * b.y; acc[2][2] += a.z * b.z; acc[2][3] += a.z * b.w;
            acc[3][0] += a.w * b.x; acc[3][1] += a.w * b.y; acc[3][2] += a.w * b.z; acc[3][3] += a.w * b.w;
        }
        __syncthreads();
    }
    #pragma unroll
    for (int ii = 0; ii < 4; ii++) {
        int row = bm + (ty << 2) + ii;
        if (row >= M) continue;
        int col = bn + (tx << 2);
        float4 bb = *(const float4*)(bias + col);
        float4 r;
        r.x = acc[ii][0] + bb.x;
        r.y = acc[ii][1] + bb.y;
        r.z = acc[ii][2] + bb.z;
        r.w = acc[ii][3] + bb.w;
        if (relu) {
            r.x = fmaxf(r.x, 0.f); r.y = fmaxf(r.y, 0.f);
            r.z = fmaxf(r.z, 0.f); r.w = fmaxf(r.w, 0.f);
        }
        *(float4*)(C + (size_t)row * N + col) = r;
    }
}

// ---------------- flash attention: 64-query tile per block ----------------
// grid (17, NHEAD, NB), 256 threads. q/k/v layout: [b, t, head*64 + d]
__global__ __launch_bounds__(256) void attn_kernel(
    const float* __restrict__ q, const float* __restrict__ k,
    const float* __restrict__ v, float* __restrict__ o)
{
    __shared__ float qs[64 * 64];   // [i][d]
    __shared__ float u [64 * 64];   // phase 1: k^T [d][j]; phase 2: p [i][j]
    __shared__ float vs[64 * 64];   // [j][d]
    int tid = threadIdx.x;
    int ty = tid >> 4, tx = tid & 15;
    int qb = blockIdx.x * 64;
    int head = blockIdx.y, b = blockIdx.z;
    const size_t bs = (size_t)T * DM;
    const float* qp = q + b * bs + head * HD;
    const float* kp = k + b * bs + head * HD;
    const float* vp = v + b * bs + head * HD;
    float* op = o + b * bs + head * HD;

    for (int idx = tid; idx < 1024; idx += 256) {
        int i = idx >> 4, c4 = (idx & 15) << 2;
        int t = qb + i;
        float4 val = make_float4(0.f, 0.f, 0.f, 0.f);
        if (t < T) val = *(const float4*)(qp + (size_t)t * DM + c4);
        val.x *= 0.125f; val.y *= 0.125f; val.z *= 0.125f; val.w *= 0.125f;
        *(float4*)&qs[i * 64 + c4] = val;
    }
    float oa[4][4] = {};
    float mloc[4] = {-1e30f, -1e30f, -1e30f, -1e30f};
    float lloc[4] = {};
    __syncthreads();

    for (int kb = 0; kb < T; kb += 64) {
        int rem = T - kb;
        // V natural
        for (int idx = tid; idx < 1024; idx += 256) {
            int j = idx >> 4, c4 = (idx & 15) << 2;
            int s = kb + j;
            float4 vv = make_float4(0.f, 0.f, 0.f, 0.f);
            if (s < T) vv = *(const float4*)(vp + (size_t)s * DM + c4);
            *(float4*)&vs[j * 64 + c4] = vv;
        }
        // K transposed into u: u[d][j]
        for (int idx = tid; idx < 1024; idx += 256) {
            int j = idx & 63, c4 = (idx >> 6) << 2;
            int s = kb + j;
            float4 kv = make_float4(0.f, 0.f, 0.f, 0.f);
            if (s < T) kv = *(const float4*)(kp + (size_t)s * DM + c4);
            u[(c4 + 0) * 64 + j] = kv.x;
            u[(c4 + 1) * 64 + j] = kv.y;
            u[(c4 + 2) * 64 + j] = kv.z;
            u[(c4 + 3) * 64 + j] = kv.w;
        }
        __syncthreads();
        // S = Q K^T tile
        float sa[4][4] = {};
        #pragma unroll 8
        for (int d = 0; d < 64; d++) {
            float4 bv = *(float4*)&u[d * 64 + (tx << 2)];
            #pragma unroll
            for (int ii = 0; ii < 4; ii++) {
                float a = qs[((ty << 2) + ii) * 64 + d];
                sa[ii][0] += a * bv.x; sa[ii][1] += a * bv.y;
                sa[ii][2] += a * bv.z; sa[ii][3] += a * bv.w;
            }
        }
        if (rem < 64) {
            #pragma unroll
            for (int jj = 0; jj < 4; jj++)
                if ((tx << 2) + jj >= rem) {
                    #pragma unroll
                    for (int ii = 0; ii < 4; ii++) sa[ii][jj] = -1e30f;
                }
        }
        __syncthreads();   // done reading K from u
        // online softmax + write P into u
        #pragma unroll
        for (int ii = 0; ii < 4; ii++) {
            float rmax = fmaxf(fmaxf(sa[ii][0], sa[ii][1]), fmaxf(sa[ii][2], sa[ii][3]));
            #pragma unroll
            for (int off = 8; off >= 1; off >>= 1)
                rmax = fmaxf(rmax, __shfl_xor_sync(0xffffffffu, rmax, off));
            float mnew = fmaxf(mloc[ii], rmax);
            float corr = __expf(mloc[ii] - mnew);
            mloc[ii] = mnew;
            float rsum = 0.f;
            #pragma unroll
            for (int jj = 0; jj < 4; jj++) {
                float p = __expf(sa[ii][jj] - mnew);
                sa[ii][jj] = p; rsum += p;
            }
            #pragma unroll
            for (int off = 8; off >= 1; off >>= 1)
                rsum += __shfl_xor_sync(0xffffffffu, rsum, off);
            lloc[ii] = lloc[ii] * corr + rsum;
            #pragma unroll
            for (int jj = 0; jj < 4; jj++) oa[ii][jj] *= corr;
            *(float4*)&u[((ty << 2) + ii) * 64 + (tx << 2)] =
                make_float4(sa[ii][0], sa[ii][1], sa[ii][2], sa[ii][3]);
        }
        __syncthreads();
        // O += P V
        #pragma unroll 8
        for (int j = 0; j < 64; j++) {
            float4 bv = *(float4*)&vs[j * 64 + (tx << 2)];
            #pragma unroll
            for (int ii = 0; ii < 4; ii++) {
                float a = u[((ty << 2) + ii) * 64 + j];
                oa[ii][0] += a * bv.x; oa[ii][1] += a * bv.y;
                oa[ii][2] += a * bv.z; oa[ii][3] += a * bv.w;
            }
        }
        __syncthreads();
    }
    #pragma unroll
    for (int ii = 0; ii < 4; ii++) {
        int t = qb + (ty << 2) + ii;
        if (t < T) {
            float inv = 1.f / lloc[ii];
            float4 r = make_float4(oa[ii][0] * inv, oa[ii][1] * inv,
                                   oa[ii][2] * inv, oa[ii][3] * inv);
            *(float4*)(op + (size_t)t * DM + (tx << 2)) = r;
        }
    }
}

// ---------------- residual add + layernorm, in-place on h ----------------
__global__ void add_ln_kernel(float* __restrict__ h, const float* __restrict__ f,
                              const float* __restrict__ gamma, const float* __restrict__ beta)
{
    int row = blockIdx.x;
    int tid = threadIdx.x;  // 128
    float* hr = h + (size_t)row * DM;
    const float* fr = f + (size_t)row * DM;
    float v[4];
    float s = 0.f;
    #pragma unroll
    for (int i = 0; i < 4; i++) {
        v[i] = hr[tid + 128 * i] + fr[tid + 128 * i];
        s += v[i];
    }
    __shared__ float sm[4];
    int lane = tid & 31, warp = tid >> 5;
    #pragma unroll
    for (int off = 16; off >= 1; off >>= 1) s += __shfl_xor_sync(0xffffffffu, s, off);
    if (lane == 0) sm[warp] = s;
    __syncthreads();
    float mean = (sm[0] + sm[1] + sm[2] + sm[3]) * (1.f / DM);
    float vs = 0.f;
    #pragma unroll
    for (int i = 0; i < 4; i++) { float d = v[i] - mean; vs += d * d; }
    __syncthreads();
    #pragma unroll
    for (int off = 16; off >= 1; off >>= 1) vs += __shfl_xor_sync(0xffffffffu, vs, off);
    if (lane == 0) sm[warp] = vs;
    __syncthreads();
    float var = (sm[0] + sm[1] + sm[2] + sm[3]) * (1.f / DM);
    float inv = rsqrtf(var + 1e-5f);
    #pragma unroll
    for (int i = 0; i < 4; i++) {
        int d = tid + 128 * i;
        hr[d] = (v[i] - mean) * inv * gamma[d] + beta[d];
    }
}

// ---------------- classification head: out = (cls@Wd1+bd1)@Wd2+bd2 ----------------
__global__ void head_kernel(const float* __restrict__ h,
                            const float* __restrict__ Wd1, const float* __restrict__ bd1,
                            const float* __restrict__ Wd2, const float* __restrict__ bd2,
                            float* __restrict__ out)
{
    __shared__ float mid[NB][MLPD];
    int tid = threadIdx.x; // 256
    for (int b = 0; b < NB; b++) {
        const float* cls = h + (size_t)b * T * DM;
        float acc = bd1[tid];
        for (int kk = 0; kk < DM; kk++)
            acc += cls[kk] * Wd1[kk * MLPD + tid];
        mid[b][tid] = acc;
    }
    __syncthreads();
    if (tid < NB * CLASSES) {
        int b = tid / CLASSES, c = tid % CLASSES;
        float acc = bd2[c];
        for (int m = 0; m < MLPD; m++)
            acc += mid[b][m] * Wd2[m * CLASSES + c];
        out[b * CLASSES + c] = acc;
    }
}

// ---------------- GAT branch: one 64-thread block per graph ----------------
__global__ __launch_bounds__(64) void gat_kernel(
    const float* __restrict__ x, const int* __restrict__ adj,
    const float* __restrict__ Wg, const float* __restrict__ ag,
    const float* __restrict__ Wgo, const float* __restrict__ ago,
    float* __restrict__ out)
{
    int gidx = blockIdx.x;              // 0..5119
    int s = gidx / 5, g = gidx % 5;
    int tid = threadIdx.x;              // 0..63 (= feature f)
    int lane = tid & 31, warp = tid >> 5;

    __shared__ float xg[5][3];
    __shared__ float hcat[5][GH * GHID];
    __shared__ float att[5][5];
    __shared__ float s1[5], s2[5];
    __shared__ float red[2][5][2];
    __shared__ int msk[25];
    __shared__ float h2[5][5];
    __shared__ float o2[5][5];

    if (tid < 15) {
        int n = tid / 3, c = tid % 3;
        xg[n][c] = x[(size_t)n * SEQ * NTOK + (size_t)s * NTOK + g * 3 + c];
    }
    if (tid < 25) msk[tid] = adj[tid];
    __syncthreads();

    for (int head = 0; head < GH; head++) {
        const float* W = Wg + head * 3 * GHID;
        float hval[5];
        #pragma unroll
        for (int n = 0; n < 5; n++)
            hval[n] = xg[n][0] * W[tid] + xg[n][1] * W[GHID + tid] + xg[n][2] * W[2 * GHID + tid];
        float a1 = ag[head * 2 * GHID + tid];
        float a2 = ag[head * 2 * GHID + GHID + tid];
        #pragma unroll
        for (int n = 0; n < 5; n++) {
            float p1 = hval[n] * a1, p2 = hval[n] * a2;
            #pragma unroll
            for (int off = 16; off >= 1; off >>= 1) {
                p1 += __shfl_xor_sync(0xffffffffu, p1, off);
                p2 += __shfl_xor_sync(0xffffffffu, p2, off);
            }
            if (lane == 0) { red[warp][n][0] = p1; red[warp][n][1] = p2; }
        }
        __syncthreads();
        if (tid < 5) {
            s1[tid] = red[0][tid][0] + red[1][tid][0];
            s2[tid] = red[0][tid][1] + red[1][tid][1];
        }
        __syncthreads();
        if (tid < 5) {
            int i = tid;
            float ev[5]; float mx = -1e30f;
            #pragma unroll
            for (int j = 0; j < 5; j++) {
                if (msk[i * 5 + j]) {
                    float e = s1[i] + s2[j];
                    e = e > 0.f ? e : 0.2f * e;
                    ev[j] = e;
                    if (e > mx) mx = e;
                } else ev[j] = -1e30f;
            }
            float sum = 0.f;
            #pragma unroll
            for (int j = 0; j < 5; j++) {
                float p = msk[i * 5 + j] ? __expf(ev[j] - mx) : 0.f;
                att[i][j] = p; sum += p;
            }
            float invs = 1.f / sum;
            #pragma unroll
            for (int j = 0; j < 5; j++) att[i][j] *= invs;
        }
        __syncthreads();
        #pragma unroll
        for (int n = 0; n < 5; n++) {
            float o = att[n][0] * hval[0] + att[n][1] * hval[1] + att[n][2] * hval[2]
                    + att[n][3] * hval[3] + att[n][4] * hval[4];
            o = o > 0.f ? o : expm1f(o);
            hcat[n][head * GHID + tid] = o;
        }
        __syncthreads();
    }

    // output GAT layer (F = GCLS = 5)
    if (tid < 25) {
        int n = tid / 5, m = tid % 5;
        float acc = 0.f;
        for (int kk = 0; kk < GH * GHID; kk++)
            acc += hcat[n][kk] * Wgo[kk * GCLS + m];
        h2[n][m] = acc;
    }
    __syncthreads();
    if (tid < 5) {
        float a1 = 0.f, a2 = 0.f;
        #pragma unroll
        for (int m = 0; m < 5; m++) {
            a1 += h2[tid][m] * ago[m];
            a2 += h2[tid][m] * ago[GCLS + m];
        }
        s1[tid] = a1; s2[tid] = a2;
    }
    __syncthreads();
    if (tid < 5) {
        int i = tid;
        float ev[5]; float mx = -1e30f;
        #pragma unroll
        for (int j = 0; j < 5; j++) {
            if (msk[i * 5 + j]) {
                float e = s1[i] + s2[j];
                e = e > 0.f ? e : 0.2f * e;
                ev[j] = e;
                if (e > mx) mx = e;
            } else ev[j] = -1e30f;
        }
        float sum = 0.f;
        #pragma unroll
        for (int j = 0; j < 5; j++) {
            float p = msk[i * 5 + j] ? __expf(ev[j] - mx) : 0.f;
            att[i][j] = p; sum += p;
        }
        float invs = 1.f / sum;
        #pragma unroll
        for (int j = 0; j < 5; j++) att[i][j] *= invs;
    }
    __syncthreads();
    if (tid < 25) {
        int n = tid / 5, m = tid % 5;
        float o = 0.f;
        #pragma unroll
        for (int j = 0; j < 5; j++) o += att[n][j] * h2[j][m];
        o = o > 0.f ? o : expm1f(o);
        o2[n][m] = o;
    }
    __syncthreads();
    if (tid < 5) {
        int n = tid;
        float mx = -1e30f;
        #pragma unroll
        for (int m = 0; m < 5; m++) mx = fmaxf(mx, o2[n][m]);
        float sum = 0.f;
        #pragma unroll
        for (int m = 0; m < 5; m++) sum += __expf(o2[n][m] - mx);
        float lse = mx + logf(sum);
        #pragma unroll
        for (int m = 0; m < 5; m++)
            out[OUT_GAT_BASE + (size_t)gidx * 25 + n * 5 + m] = o2[n][m] - lse;
    }
}

// ---------------- host orchestration ----------------
extern "C" void kernel_launch(void* const* d_in, const int* in_sizes, int n_in,
                              void* d_out, int out_size)
{
    const float* x       = (const float*)d_in[0];
    const int*   adj     = (const int*)  d_in[1];
    const float* W_enc   = (const float*)d_in[2];
    const float* b_enc   = (const float*)d_in[3];
    const float* cls_tok = (const float*)d_in[4];
    const float* pos_emb = (const float*)d_in[5];
    const float* Wq      = (const float*)d_in[6];
    const float* bq      = (const float*)d_in[7];
    const float* Wk      = (const float*)d_in[8];
    const float* bk      = (const float*)d_in[9];
    const float* Wv      = (const float*)d_in[10];
    const float* bv      = (const float*)d_in[11];
    const float* Wo      = (const float*)d_in[12];
    const float* bo      = (const float*)d_in[13];
    const float* W1      = (const float*)d_in[14];
    const float* b1      = (const float*)d_in[15];
    const float* W2      = (const float*)d_in[16];
    const float* b2      = (const float*)d_in[17];
    const float* g1      = (const float*)d_in[18];
    const float* be1     = (const float*)d_in[19];
    const float* g2      = (const float*)d_in[20];
    const float* be2     = (const float*)d_in[21];
    const float* Wd1     = (const float*)d_in[22];
    const float* bd1     = (const float*)d_in[23];
    const float* Wd2     = (const float*)d_in[24];
    const float* bd2     = (const float*)d_in[25];
    const float* Wg      = (const float*)d_in[26];
    const float* ag      = (const float*)d_in[27];
    const float* Wgo     = (const float*)d_in[28];
    const float* ago     = (const float*)d_in[29];
    float* out = (float*)d_out;

    float *h, *q, *k, *v, *ao, *t, *ff;
    cudaGetSymbolAddress((void**)&h,  g_h);
    cudaGetSymbolAddress((void**)&q,  g_q);
    cudaGetSymbolAddress((void**)&k,  g_k);
    cudaGetSymbolAddress((void**)&v,  g_v);
    cudaGetSymbolAddress((void**)&ao, g_ao);
    cudaGetSymbolAddress((void**)&t,  g_t);
    cudaGetSymbolAddress((void**)&ff, g_ff);

    // GAT branch (independent)
    gat_kernel<<<GAT_GRAPHS, 64>>>(x, adj, Wg, ag, Wgo, ago, out);

    // encoder
    enc_kernel<<<MROWS, 128>>>(x, W_enc, b_enc, cls_tok, pos_emb, h);

    dim3 gemm_tb(256);
    dim3 grid_dm(DM / 64, (MROWS + 63) / 64);    // N=512
    dim3 grid_ff(DFF / 64, (MROWS + 63) / 64);   // N=2048
    dim3 attn_grid((T + 63) / 64, NHEAD, NB);

    for (int l = 0; l < NL; l++) {
        gemm_kernel<<<grid_dm, gemm_tb>>>(h, Wq + (size_t)l * DM * DM, bq + l * DM, q, MROWS, DM, DM, 0);
        gemm_kernel<<<grid_dm, gemm_tb>>>(h, Wk + (size_t)l * DM * DM, bk + l * DM, k, MROWS, DM, DM, 0);
        gemm_kernel<<<grid_dm, gemm_tb>>>(h, Wv + (size_t)l * DM * DM, bv + l * DM, v, MROWS, DM, DM, 0);
        attn_kernel<<<attn_grid, 256>>>(q, k, v, ao);
        gemm_kernel<<<grid_dm, gemm_tb>>>(ao, Wo + (size_t)l * DM * DM, bo + l * DM, t, MROWS, DM, DM, 0);
        add_ln_kernel<<<MROWS, 128>>>(h, t, g1 + l * DM, be1 + l * DM);
        gemm_kernel<<<grid_ff, gemm_tb>>>(h, W1 + (size_t)l * DM * DFF, b1 + l * DFF, ff, MROWS, DFF, DM, 1);
        gemm_kernel<<<grid_dm, gemm_tb>>>(ff, W2 + (size_t)l * DFF * DM, b2 + l * DM, t, MROWS, DM, DFF, 0);
        add_ln_kernel<<<MROWS, 128>>>(h, t, g2 + l * DM, be2 + l * DM);
    }

    head_kernel<<<1, 256>>>(h, Wd1, bd1, Wd2, bd2, out);
}